// round 1
// baseline (speedup 1.0000x reference)
#include <cuda_runtime.h>
#include <math.h>

// Problem constants (fixed shapes from reference setup_inputs)
#define S_TOT    8192      // B*T = 4*2048
#define C_DIM    1024
#define E_NUM    8
#define H_DIM    4096
#define CAPACITY 2560      // ceil(1.25 * 8192 * 2 / 8)

// ---------------------------------------------------------------------------
// Device scratch (static __device__ arrays: no allocation at runtime)
// ---------------------------------------------------------------------------
__device__ int   g_cnt[E_NUM];
__device__ float g_probsum[E_NUM];
__device__ int   g_tok[E_NUM * S_TOT];
__device__ float g_gate[E_NUM * S_TOT];
__device__ int   g_kept[E_NUM];
__device__ int   g_ktok[E_NUM * CAPACITY];
__device__ float g_kgate[E_NUM * CAPACITY];
__device__ float g_h[(size_t)E_NUM * CAPACITY * H_DIM];   // 335 MB intermediate

// ---------------------------------------------------------------------------
// 0) Zero output y region + per-launch counters (graph replays reuse globals)
// ---------------------------------------------------------------------------
__global__ void zero_kernel(float* __restrict__ y, int ny) {
    int stride = gridDim.x * blockDim.x;
    for (int i = blockIdx.x * blockDim.x + threadIdx.x; i < ny; i += stride)
        y[i] = 0.0f;
    if (blockIdx.x == 0 && threadIdx.x < E_NUM) {
        g_cnt[threadIdx.x] = 0;
        g_probsum[threadIdx.x] = 0.0f;
    }
}

// ---------------------------------------------------------------------------
// 1) Router: logits -> softmax -> top2 -> append to per-expert lists
//    One warp per token, router_w transposed into smem for conflict-free reads.
// ---------------------------------------------------------------------------
__global__ void router_kernel(const float* __restrict__ x,
                              const float* __restrict__ rw,
                              const float* __restrict__ rb) {
    __shared__ float swT[E_NUM][C_DIM];   // 32 KB, [e][c]
    int tid = threadIdx.x;
    for (int i = tid; i < C_DIM * E_NUM; i += 256) {
        int c = i / E_NUM, e = i % E_NUM;   // rw is [C, E] row-major
        swT[e][c] = rw[i];
    }
    __syncthreads();

    int warp = tid >> 5, lane = tid & 31;
    int s = blockIdx.x * 8 + warp;
    const float* xr = x + (size_t)s * C_DIM;

    float acc[E_NUM];
#pragma unroll
    for (int e = 0; e < E_NUM; e++) acc[e] = 0.0f;

    for (int c = lane; c < C_DIM; c += 32) {
        float xv = xr[c];
#pragma unroll
        for (int e = 0; e < E_NUM; e++) acc[e] += xv * swT[e][c];
    }
#pragma unroll
    for (int e = 0; e < E_NUM; e++) {
#pragma unroll
        for (int o = 16; o > 0; o >>= 1)
            acc[e] += __shfl_xor_sync(0xffffffff, acc[e], o);
    }

    if (lane == 0) {
        float logit[E_NUM], p[E_NUM];
        float m = -1e30f;
#pragma unroll
        for (int e = 0; e < E_NUM; e++) {
            logit[e] = acc[e] + rb[e];
            m = fmaxf(m, logit[e]);
        }
        float sum = 0.0f;
#pragma unroll
        for (int e = 0; e < E_NUM; e++) { p[e] = expf(logit[e] - m); sum += p[e]; }
        float inv = 1.0f / sum;
#pragma unroll
        for (int e = 0; e < E_NUM; e++) p[e] *= inv;

        // top-2 (ties -> lower index, matching lax.top_k)
        int e1 = 0;
#pragma unroll
        for (int e = 1; e < E_NUM; e++) if (p[e] > p[e1]) e1 = e;
        int e2 = (e1 == 0) ? 1 : 0;
#pragma unroll
        for (int e = 0; e < E_NUM; e++)
            if (e != e1 && e != e2 && p[e] > p[e2]) e2 = e;

#pragma unroll
        for (int e = 0; e < E_NUM; e++) atomicAdd(&g_probsum[e], p[e]);

        int pos = atomicAdd(&g_cnt[e1], 1);
        g_tok[e1 * S_TOT + pos] = s;  g_gate[e1 * S_TOT + pos] = p[e1];
        pos = atomicAdd(&g_cnt[e2], 1);
        g_tok[e2 * S_TOT + pos] = s;  g_gate[e2 * S_TOT + pos] = p[e2];
    }
}

// ---------------------------------------------------------------------------
// 2) Capacity filter. Fast path: all kept (expected case). Slow path (rare):
//    rank = #{j : g_j > g_i or (g_j == g_i and tok_j < tok_i)}, keep rank < cap.
// ---------------------------------------------------------------------------
__global__ void capacity_kernel() {
    int e = blockIdx.x;
    int tid = threadIdx.x;
    int n = g_cnt[e];
    const int*   tl = g_tok  + e * S_TOT;
    const float* gl = g_gate + e * S_TOT;

    if (n <= CAPACITY) {
        if (tid == 0) g_kept[e] = n;
        for (int i = tid; i < n; i += blockDim.x) {
            g_ktok[e * CAPACITY + i]  = tl[i];
            g_kgate[e * CAPACITY + i] = gl[i];
        }
    } else {
        if (tid == 0) g_kept[e] = CAPACITY;
        for (int i = tid; i < n; i += blockDim.x) {
            float gi = gl[i]; int ti = tl[i];
            int rank = 0;
            for (int j = 0; j < n; j++) {
                float gj = gl[j];
                rank += (gj > gi) || (gj == gi && tl[j] < ti);
            }
            if (rank < CAPACITY) {
                g_ktok[e * CAPACITY + rank]  = ti;
                g_kgate[e * CAPACITY + rank] = gi;
            }
        }
    }
}

// ---------------------------------------------------------------------------
// 3) GEMM1: h[e,m,:] = gelu( x[tok[m],:] @ w1[e] + b1[e] )
//    128x128 tile, K-tile 8, 256 threads, 8x8 register tile per thread.
// ---------------------------------------------------------------------------
__global__ void __launch_bounds__(256, 2)
gemm1_kernel(const float* __restrict__ x,
             const float* __restrict__ w1,
             const float* __restrict__ b1) {
    int e  = blockIdx.z;
    int m0 = blockIdx.y * 128;
    int n0 = blockIdx.x * 128;
    int kept = g_kept[e];
    if (m0 >= kept) return;

    __shared__ float As[8][128];
    __shared__ float Bs[8][128];
    __shared__ int   toks[128];

    int tid = threadIdx.x;
    if (tid < 128) {
        int m = m0 + tid;
        toks[tid] = (m < kept) ? g_ktok[e * CAPACITY + m] : -1;
    }
    __syncthreads();

    const float* Bg = w1 + (size_t)e * C_DIM * H_DIM;

    float acc[8][8];
#pragma unroll
    for (int i = 0; i < 8; i++)
#pragma unroll
        for (int j = 0; j < 8; j++) acc[i][j] = 0.0f;

    int ar = tid >> 1, ak = (tid & 1) * 4;     // A load: 2 threads per row
    int bk = tid >> 5, bn = (tid & 31) * 4;    // B load: row k, float4 cols
    int trow = tid >> 4, tcol = tid & 15;

    int atok = toks[ar];
    const float* arow = (atok >= 0) ? (x + (size_t)atok * C_DIM) : x;

    for (int k0 = 0; k0 < C_DIM; k0 += 8) {
        float4 av = make_float4(0.f, 0.f, 0.f, 0.f);
        if (atok >= 0) av = *(const float4*)(arow + k0 + ak);
        float4 bv = *(const float4*)(Bg + (size_t)(k0 + bk) * H_DIM + n0 + bn);

        As[ak + 0][ar] = av.x; As[ak + 1][ar] = av.y;
        As[ak + 2][ar] = av.z; As[ak + 3][ar] = av.w;
        *(float4*)&Bs[bk][bn] = bv;
        __syncthreads();

#pragma unroll
        for (int kk = 0; kk < 8; kk++) {
            float4 a0 = *(const float4*)&As[kk][trow * 8];
            float4 a1 = *(const float4*)&As[kk][trow * 8 + 4];
            float4 b0 = *(const float4*)&Bs[kk][tcol * 8];
            float4 b1v = *(const float4*)&Bs[kk][tcol * 8 + 4];
            float a[8] = {a0.x, a0.y, a0.z, a0.w, a1.x, a1.y, a1.z, a1.w};
            float b[8] = {b0.x, b0.y, b0.z, b0.w, b1v.x, b1v.y, b1v.z, b1v.w};
#pragma unroll
            for (int i = 0; i < 8; i++)
#pragma unroll
                for (int j = 0; j < 8; j++)
                    acc[i][j] = fmaf(a[i], b[j], acc[i][j]);
        }
        __syncthreads();
    }

    float* hp = g_h + (size_t)e * CAPACITY * H_DIM;
    const float* b1e = b1 + (size_t)e * H_DIM;
#pragma unroll
    for (int i = 0; i < 8; i++) {
        int m = m0 + trow * 8 + i;
        if (m >= kept) continue;
#pragma unroll
        for (int j = 0; j < 8; j++) {
            int n = n0 + tcol * 8 + j;
            float v = acc[i][j] + b1e[n];
            // exact gelu: 0.5*v*(1+erf(v/sqrt(2)))
            v = 0.5f * v * (1.0f + erff(v * 0.70710678118654752f));
            hp[(size_t)m * H_DIM + n] = v;
        }
    }
}

// ---------------------------------------------------------------------------
// 4) GEMM2: y[tok[m],:] += gate[m] * ( h[e,m,:] @ w2[e] + b2[e] )
// ---------------------------------------------------------------------------
__global__ void __launch_bounds__(256, 2)
gemm2_kernel(const float* __restrict__ w2,
             const float* __restrict__ b2,
             float* __restrict__ y) {
    int e  = blockIdx.z;
    int m0 = blockIdx.y * 128;
    int n0 = blockIdx.x * 128;
    int kept = g_kept[e];
    if (m0 >= kept) return;

    __shared__ float As[8][128];
    __shared__ float Bs[8][128];

    int tid = threadIdx.x;
    const float* Ag = g_h + (size_t)e * CAPACITY * H_DIM;
    const float* Bg = w2 + (size_t)e * H_DIM * C_DIM;

    float acc[8][8];
#pragma unroll
    for (int i = 0; i < 8; i++)
#pragma unroll
        for (int j = 0; j < 8; j++) acc[i][j] = 0.0f;

    int ar = tid >> 1, ak = (tid & 1) * 4;
    int bk = tid >> 5, bn = (tid & 31) * 4;
    int trow = tid >> 4, tcol = tid & 15;

    const float* arow = Ag + (size_t)(m0 + ar) * H_DIM;   // rows >= kept read zeros (never written)

    for (int k0 = 0; k0 < H_DIM; k0 += 8) {
        float4 av = *(const float4*)(arow + k0 + ak);
        float4 bv = *(const float4*)(Bg + (size_t)(k0 + bk) * C_DIM + n0 + bn);

        As[ak + 0][ar] = av.x; As[ak + 1][ar] = av.y;
        As[ak + 2][ar] = av.z; As[ak + 3][ar] = av.w;
        *(float4*)&Bs[bk][bn] = bv;
        __syncthreads();

#pragma unroll
        for (int kk = 0; kk < 8; kk++) {
            float4 a0 = *(const float4*)&As[kk][trow * 8];
            float4 a1 = *(const float4*)&As[kk][trow * 8 + 4];
            float4 b0 = *(const float4*)&Bs[kk][tcol * 8];
            float4 b1v = *(const float4*)&Bs[kk][tcol * 8 + 4];
            float a[8] = {a0.x, a0.y, a0.z, a0.w, a1.x, a1.y, a1.z, a1.w};
            float b[8] = {b0.x, b0.y, b0.z, b0.w, b1v.x, b1v.y, b1v.z, b1v.w};
#pragma unroll
            for (int i = 0; i < 8; i++)
#pragma unroll
                for (int j = 0; j < 8; j++)
                    acc[i][j] = fmaf(a[i], b[j], acc[i][j]);
        }
        __syncthreads();
    }

    const float* b2e = b2 + (size_t)e * C_DIM;
#pragma unroll
    for (int i = 0; i < 8; i++) {
        int m = m0 + trow * 8 + i;
        if (m >= kept) continue;
        int   tok  = g_ktok[e * CAPACITY + m];
        float gate = g_kgate[e * CAPACITY + m];
        float* yrow = y + (size_t)tok * C_DIM;
#pragma unroll
        for (int j = 0; j < 8; j++) {
            int n = n0 + tcol * 8 + j;
            float v = (acc[i][j] + b2e[n]) * gate;
            atomicAdd(&yrow[n], v);
        }
    }
}

// ---------------------------------------------------------------------------
// 5) Aux loss
// ---------------------------------------------------------------------------
__global__ void aux_kernel(float* __restrict__ out, int aux_idx) {
    if (threadIdx.x == 0 && blockIdx.x == 0) {
        float tot = 0.0f;
        for (int e = 0; e < E_NUM; e++) tot += (float)g_kept[e];
        float aux = 0.0f;
        for (int e = 0; e < E_NUM; e++) {
            float mean_p = g_probsum[e] / (float)S_TOT;
            float frac   = (float)g_kept[e] / (tot + 1e-9f);
            aux += mean_p * frac;
        }
        out[aux_idx] = aux * (float)E_NUM;
    }
}

// ---------------------------------------------------------------------------
// Launch
// ---------------------------------------------------------------------------
extern "C" void kernel_launch(void* const* d_in, const int* in_sizes, int n_in,
                              void* d_out, int out_size) {
    const float* x   = (const float*)d_in[0];
    const float* rw  = (const float*)d_in[1];
    const float* rb  = (const float*)d_in[2];
    const float* w1  = (const float*)d_in[3];
    const float* b1  = (const float*)d_in[4];
    const float* w2  = (const float*)d_in[5];
    const float* b2  = (const float*)d_in[6];
    float* out = (float*)d_out;

    int ny = out_size - 1;   // y elements; last element = aux loss

    zero_kernel<<<1024, 256>>>(out, ny);
    router_kernel<<<S_TOT / 8, 256>>>(x, rw, rb);
    capacity_kernel<<<E_NUM, 256>>>();
    {
        dim3 grid(H_DIM / 128, CAPACITY / 128, E_NUM);   // 32 x 20 x 8
        gemm1_kernel<<<grid, 256>>>(x, w1, b1);
    }
    {
        dim3 grid(C_DIM / 128, CAPACITY / 128, E_NUM);   // 8 x 20 x 8
        gemm2_kernel<<<grid, 256>>>(w2, b2, out);
    }
    aux_kernel<<<1, 32>>>(out, ny);
}

// round 8
// speedup vs baseline: 3.1189x; 3.1189x over previous
#include <cuda_runtime.h>
#include <mma.h>
#include <math.h>
#include <stdint.h>

// Problem constants (fixed shapes from reference setup_inputs)
#define S_TOT    8192      // B*T
#define C_DIM    1024
#define E_NUM    8
#define H_DIM    4096
#define CAPACITY 2560      // ceil(1.25 * 8192 * 2 / 8)

// GEMM tiling: CTA 128x128x16, 8 warps (2x4), warp tile 64x32, 2-buffer static smem
#define BM 128
#define BN 128
#define BK 16
#define ROWF 20            // floats per smem row (16 data + 4 pad = 80 bytes)

// ---------------------------------------------------------------------------
// Device scratch — EXACTLY the round-1 (passing) set. No g_xr / g_w1T / g_w2T.
// ---------------------------------------------------------------------------
__device__ int   g_cnt[E_NUM];
__device__ float g_probsum[E_NUM];
__device__ int   g_tok[E_NUM * S_TOT];
__device__ float g_gate[E_NUM * S_TOT];
__device__ int   g_kept[E_NUM];
__device__ int   g_ktok[E_NUM * CAPACITY];
__device__ float g_kgate[E_NUM * CAPACITY];
__device__ float g_h[(size_t)E_NUM * CAPACITY * H_DIM];   // tf32-rounded activations

// ---------------------------------------------------------------------------
// Helpers
// ---------------------------------------------------------------------------
__device__ __forceinline__ float rna_tf32(float v) {
    return nvcuda::wmma::__float_to_tf32(v);   // cvt.rna.tf32.f32, intrinsic form
}
__device__ __forceinline__ uint32_t smem_addr(const void* p) {
    return (uint32_t)__cvta_generic_to_shared(p);
}

#define LDSM4(r, addr) \
    asm volatile("ldmatrix.sync.aligned.m8n8.x4.shared.b16 {%0,%1,%2,%3}, [%4];" \
        : "=r"((r)[0]), "=r"((r)[1]), "=r"((r)[2]), "=r"((r)[3]) : "r"(addr))

#define MMA_TF32(d, a, b0, b1) \
    asm volatile("mma.sync.aligned.m16n8k8.row.col.f32.tf32.tf32.f32 " \
        "{%0,%1,%2,%3}, {%4,%5,%6,%7}, {%8,%9}, {%0,%1,%2,%3};" \
        : "+f"((d)[0]), "+f"((d)[1]), "+f"((d)[2]), "+f"((d)[3]) \
        : "r"((a)[0]), "r"((a)[1]), "r"((a)[2]), "r"((a)[3]), "r"(b0), "r"(b1))

// ---------------------------------------------------------------------------
// 0) Zero output + counters
// ---------------------------------------------------------------------------
__global__ void zero_kernel(float* __restrict__ y, int ny) {
    int stride = gridDim.x * blockDim.x;
    for (int i = blockIdx.x * blockDim.x + threadIdx.x; i < ny; i += stride)
        y[i] = 0.0f;
    if (blockIdx.x == 0 && threadIdx.x < E_NUM) {
        g_cnt[threadIdx.x] = 0;
        g_probsum[threadIdx.x] = 0.0f;
    }
}

// ---------------------------------------------------------------------------
// 1) Router
// ---------------------------------------------------------------------------
__global__ void router_kernel(const float* __restrict__ x,
                              const float* __restrict__ rw,
                              const float* __restrict__ rb) {
    __shared__ float swT[E_NUM][C_DIM];
    int tid = threadIdx.x;
    for (int i = tid; i < C_DIM * E_NUM; i += 256) {
        int c = i / E_NUM, e = i % E_NUM;
        swT[e][c] = rw[i];
    }
    __syncthreads();

    int warp = tid >> 5, lane = tid & 31;
    int s = blockIdx.x * 8 + warp;
    const float* xr = x + (size_t)s * C_DIM;

    float acc[E_NUM];
#pragma unroll
    for (int e = 0; e < E_NUM; e++) acc[e] = 0.0f;
    for (int c = lane; c < C_DIM; c += 32) {
        float xv = xr[c];
#pragma unroll
        for (int e = 0; e < E_NUM; e++) acc[e] += xv * swT[e][c];
    }
#pragma unroll
    for (int e = 0; e < E_NUM; e++) {
#pragma unroll
        for (int o = 16; o > 0; o >>= 1)
            acc[e] += __shfl_xor_sync(0xffffffff, acc[e], o);
    }
    if (lane == 0) {
        float logit[E_NUM], p[E_NUM];
        float m = -1e30f;
#pragma unroll
        for (int e = 0; e < E_NUM; e++) { logit[e] = acc[e] + rb[e]; m = fmaxf(m, logit[e]); }
        float sum = 0.0f;
#pragma unroll
        for (int e = 0; e < E_NUM; e++) { p[e] = expf(logit[e] - m); sum += p[e]; }
        float inv = 1.0f / sum;
#pragma unroll
        for (int e = 0; e < E_NUM; e++) p[e] *= inv;

        int e1 = 0;
#pragma unroll
        for (int e = 1; e < E_NUM; e++) if (p[e] > p[e1]) e1 = e;
        int e2 = (e1 == 0) ? 1 : 0;
#pragma unroll
        for (int e = 0; e < E_NUM; e++)
            if (e != e1 && e != e2 && p[e] > p[e2]) e2 = e;
#pragma unroll
        for (int e = 0; e < E_NUM; e++) atomicAdd(&g_probsum[e], p[e]);

        int pos = atomicAdd(&g_cnt[e1], 1);
        g_tok[e1 * S_TOT + pos] = s;  g_gate[e1 * S_TOT + pos] = p[e1];
        pos = atomicAdd(&g_cnt[e2], 1);
        g_tok[e2 * S_TOT + pos] = s;  g_gate[e2 * S_TOT + pos] = p[e2];
    }
}

// ---------------------------------------------------------------------------
// 2) Capacity filter
// ---------------------------------------------------------------------------
__global__ void capacity_kernel() {
    int e = blockIdx.x;
    int tid = threadIdx.x;
    int n = g_cnt[e];
    const int*   tl = g_tok  + e * S_TOT;
    const float* gl = g_gate + e * S_TOT;

    if (n <= CAPACITY) {
        if (tid == 0) g_kept[e] = n;
        for (int i = tid; i < n; i += blockDim.x) {
            g_ktok[e * CAPACITY + i]  = tl[i];
            g_kgate[e * CAPACITY + i] = gl[i];
        }
    } else {
        if (tid == 0) g_kept[e] = CAPACITY;
        for (int i = tid; i < n; i += blockDim.x) {
            float gi = gl[i]; int ti = tl[i];
            int rank = 0;
            for (int j = 0; j < n; j++) {
                float gj = gl[j];
                rank += (gj > gi) || (gj == gi && tl[j] < ti);
            }
            if (rank < CAPACITY) {
                g_ktok[e * CAPACITY + rank]  = ti;
                g_kgate[e * CAPACITY + rank] = gi;
            }
        }
    }
}

// ---------------------------------------------------------------------------
// 3) GEMM1 (tf32 mma.sync): h[e,m,:] = rna(gelu(x[tok[m],:] @ w1[e] + b1[e]))
//    A: gather rows of x, rna on load. B: w1 [C][H] k-major, transposed into
//    n-major smem rows on the fly (4 coalesced scalar loads -> 1 float4 store).
// ---------------------------------------------------------------------------
__global__ void __launch_bounds__(256)
gemm1_mma(const float* __restrict__ x,
          const float* __restrict__ w1,
          const float* __restrict__ b1) {
    __shared__ __align__(16) float sA[2][BM * ROWF];   // 10 KB x2
    __shared__ __align__(16) float sB[2][BN * ROWF];   // 10 KB x2
    __shared__ int s_tok[BM];

    int e  = blockIdx.z;
    int m0 = blockIdx.y * BM;
    int n0 = blockIdx.x * BN;
    int kept = g_kept[e];
    if (m0 >= kept) return;

    int tid  = threadIdx.x;
    int lane = tid & 31;
    int wid  = tid >> 5;
    int wm = (wid & 1) * 64;
    int wn = (wid >> 1) * 32;

    if (tid < BM) {
        int m = m0 + tid;
        s_tok[tid] = (m < kept) ? g_ktok[e * CAPACITY + m] : 0;  // clamp; masked in epilogue
    }
    __syncthreads();

    // ldmatrix fragment byte offsets within one buffer (80 B pitch)
    int rowA_lm = (lane & 7) + ((lane >> 3) & 1) * 8;
    int khA = (lane >> 4);
    uint32_t aoff[4];
#pragma unroll
    for (int tm = 0; tm < 4; tm++)
        aoff[tm] = (uint32_t)(wm + tm * 16 + rowA_lm) * 80u + khA * 16u;
    int nB_lm = (lane & 7) + (lane >> 4) * 8;
    int khB = (lane >> 3) & 1;
    uint32_t boff[2];
#pragma unroll
    for (int tp = 0; tp < 2; tp++)
        boff[tp] = (uint32_t)(wn + tp * 16 + nB_lm) * 80u + khB * 16u;

    uint32_t baseA0 = smem_addr(&sA[0][0]), baseA1 = smem_addr(&sA[1][0]);
    uint32_t baseB0 = smem_addr(&sB[0][0]), baseB1 = smem_addr(&sB[1][0]);

    // A staging: thread covers rows r and r+64, 16B chunk ch (rna applied on load)
    int r = tid >> 2, ch = tid & 3;
    const float* pA0 = x + (size_t)s_tok[r] * C_DIM + ch * 4;
    const float* pA1 = x + (size_t)s_tok[r + 64] * C_DIM + ch * 4;
    int sa0 = r * ROWF + ch * 4;
    int sa1 = (r + 64) * ROWF + ch * 4;

    // B staging: thread handles column n (of 128) for k-quads kqb and kqb+2
    int nb = tid & 127;
    int kqb = tid >> 7;           // 0 or 1
    const float* pB = w1 + (size_t)e * C_DIM * H_DIM + n0 + nb;   // + k*H_DIM
    int sb0 = nb * ROWF + kqb * 4;
    int sb1 = nb * ROWF + (kqb + 2) * 4;

    float acc[4][4][4];
#pragma unroll
    for (int i = 0; i < 4; i++)
#pragma unroll
        for (int j = 0; j < 4; j++)
#pragma unroll
            for (int k = 0; k < 4; k++) acc[i][j][k] = 0.0f;

    const int NCHUNK = C_DIM / BK;   // 64

    // prologue: fill buffer 0 (k0 = 0)
    {
        float4 va0 = *(const float4*)pA0;
        float4 va1 = *(const float4*)pA1;
        va0.x = rna_tf32(va0.x); va0.y = rna_tf32(va0.y); va0.z = rna_tf32(va0.z); va0.w = rna_tf32(va0.w);
        va1.x = rna_tf32(va1.x); va1.y = rna_tf32(va1.y); va1.z = rna_tf32(va1.z); va1.w = rna_tf32(va1.w);
        *(float4*)&sA[0][sa0] = va0;
        *(float4*)&sA[0][sa1] = va1;
        float4 vb0, vb1;
        vb0.x = rna_tf32(pB[(size_t)(kqb * 4 + 0) * H_DIM]);
        vb0.y = rna_tf32(pB[(size_t)(kqb * 4 + 1) * H_DIM]);
        vb0.z = rna_tf32(pB[(size_t)(kqb * 4 + 2) * H_DIM]);
        vb0.w = rna_tf32(pB[(size_t)(kqb * 4 + 3) * H_DIM]);
        vb1.x = rna_tf32(pB[(size_t)((kqb + 2) * 4 + 0) * H_DIM]);
        vb1.y = rna_tf32(pB[(size_t)((kqb + 2) * 4 + 1) * H_DIM]);
        vb1.z = rna_tf32(pB[(size_t)((kqb + 2) * 4 + 2) * H_DIM]);
        vb1.w = rna_tf32(pB[(size_t)((kqb + 2) * 4 + 3) * H_DIM]);
        *(float4*)&sB[0][sb0] = vb0;
        *(float4*)&sB[0][sb1] = vb1;
    }
    __syncthreads();

    for (int c = 0; c < NCHUNK; c++) {
        int buf = c & 1;
        float4 va0, va1, vb0, vb1;
        if (c + 1 < NCHUNK) {
            int k0 = (c + 1) * BK;
            va0 = *(const float4*)(pA0 + k0);
            va1 = *(const float4*)(pA1 + k0);
            va0.x = rna_tf32(va0.x); va0.y = rna_tf32(va0.y); va0.z = rna_tf32(va0.z); va0.w = rna_tf32(va0.w);
            va1.x = rna_tf32(va1.x); va1.y = rna_tf32(va1.y); va1.z = rna_tf32(va1.z); va1.w = rna_tf32(va1.w);
            vb0.x = rna_tf32(pB[(size_t)(k0 + kqb * 4 + 0) * H_DIM]);
            vb0.y = rna_tf32(pB[(size_t)(k0 + kqb * 4 + 1) * H_DIM]);
            vb0.z = rna_tf32(pB[(size_t)(k0 + kqb * 4 + 2) * H_DIM]);
            vb0.w = rna_tf32(pB[(size_t)(k0 + kqb * 4 + 3) * H_DIM]);
            vb1.x = rna_tf32(pB[(size_t)(k0 + (kqb + 2) * 4 + 0) * H_DIM]);
            vb1.y = rna_tf32(pB[(size_t)(k0 + (kqb + 2) * 4 + 1) * H_DIM]);
            vb1.z = rna_tf32(pB[(size_t)(k0 + (kqb + 2) * 4 + 2) * H_DIM]);
            vb1.w = rna_tf32(pB[(size_t)(k0 + (kqb + 2) * 4 + 3) * H_DIM]);
        }

        uint32_t bA = buf ? baseA1 : baseA0;
        uint32_t bB = buf ? baseB1 : baseB0;
#pragma unroll
        for (int ks = 0; ks < 2; ks++) {
            uint32_t a[4][4], b[2][4];
#pragma unroll
            for (int tm = 0; tm < 4; tm++) LDSM4(a[tm], bA + aoff[tm] + ks * 32);
#pragma unroll
            for (int tp = 0; tp < 2; tp++) LDSM4(b[tp], bB + boff[tp] + ks * 32);
#pragma unroll
            for (int tm = 0; tm < 4; tm++)
#pragma unroll
                for (int tn = 0; tn < 4; tn++)
                    MMA_TF32(acc[tm][tn], a[tm], b[tn >> 1][(tn & 1) * 2], b[tn >> 1][(tn & 1) * 2 + 1]);
        }

        if (c + 1 < NCHUNK) {
            int nbuf = buf ^ 1;
            *(float4*)&sA[nbuf][sa0] = va0;
            *(float4*)&sA[nbuf][sa1] = va1;
            *(float4*)&sB[nbuf][sb0] = vb0;
            *(float4*)&sB[nbuf][sb1] = vb1;
        }
        __syncthreads();
    }

    // Epilogue: bias + exact gelu + rna round
    const float* b1e = b1 + (size_t)e * H_DIM;
    float* hbase = g_h + (size_t)e * CAPACITY * H_DIM;
    int r0 = lane >> 2, cb = (lane & 3) * 2;
#pragma unroll
    for (int tm = 0; tm < 4; tm++) {
#pragma unroll
        for (int half = 0; half < 2; half++) {
            int m = m0 + wm + tm * 16 + r0 + half * 8;
            if (m >= kept) continue;
            float* hrow = hbase + (size_t)m * H_DIM;
#pragma unroll
            for (int tn = 0; tn < 4; tn++) {
                int col = n0 + wn + tn * 8 + cb;
                float v0 = acc[tm][tn][half * 2]     + b1e[col];
                float v1 = acc[tm][tn][half * 2 + 1] + b1e[col + 1];
                v0 = 0.5f * v0 * (1.0f + erff(v0 * 0.70710678118654752f));
                v1 = 0.5f * v1 * (1.0f + erff(v1 * 0.70710678118654752f));
                float2 out2 = make_float2(rna_tf32(v0), rna_tf32(v1));
                *(float2*)(hrow + col) = out2;
            }
        }
    }
}

// ---------------------------------------------------------------------------
// 4) GEMM2 (tf32 mma.sync): y[tok[m],:] += gate[m]*(h[e,m,:] @ w2[e] + b2[e])
//    A: g_h rows (already tf32-rounded). B: w2 [H][C] transposed on the fly.
// ---------------------------------------------------------------------------
__global__ void __launch_bounds__(256)
gemm2_mma(const float* __restrict__ w2,
          const float* __restrict__ b2,
          float* __restrict__ y) {
    __shared__ __align__(16) float sA[2][BM * ROWF];
    __shared__ __align__(16) float sB[2][BN * ROWF];
    __shared__ int   s_tok[BM];
    __shared__ float s_gate[BM];

    int e  = blockIdx.z;
    int m0 = blockIdx.y * BM;
    int n0 = blockIdx.x * BN;
    int kept = g_kept[e];
    if (m0 >= kept) return;

    int tid  = threadIdx.x;
    int lane = tid & 31;
    int wid  = tid >> 5;
    int wm = (wid & 1) * 64;
    int wn = (wid >> 1) * 32;

    if (tid < BM) {
        int m = m0 + tid;
        s_tok[tid]  = (m < kept) ? g_ktok[e * CAPACITY + m]  : 0;
        s_gate[tid] = (m < kept) ? g_kgate[e * CAPACITY + m] : 0.0f;
    }
    __syncthreads();

    int rowA_lm = (lane & 7) + ((lane >> 3) & 1) * 8;
    int khA = (lane >> 4);
    uint32_t aoff[4];
#pragma unroll
    for (int tm = 0; tm < 4; tm++)
        aoff[tm] = (uint32_t)(wm + tm * 16 + rowA_lm) * 80u + khA * 16u;
    int nB_lm = (lane & 7) + (lane >> 4) * 8;
    int khB = (lane >> 3) & 1;
    uint32_t boff[2];
#pragma unroll
    for (int tp = 0; tp < 2; tp++)
        boff[tp] = (uint32_t)(wn + tp * 16 + nB_lm) * 80u + khB * 16u;

    uint32_t baseA0 = smem_addr(&sA[0][0]), baseA1 = smem_addr(&sA[1][0]);
    uint32_t baseB0 = smem_addr(&sB[0][0]), baseB1 = smem_addr(&sB[1][0]);

    int r = tid >> 2, ch = tid & 3;
    const float* hbase = g_h + (size_t)e * CAPACITY * H_DIM;
    const float* pA0 = hbase + (size_t)(m0 + r) * H_DIM + ch * 4;        // rows >= kept: stale but masked
    const float* pA1 = hbase + (size_t)(m0 + r + 64) * H_DIM + ch * 4;
    int sa0 = r * ROWF + ch * 4;
    int sa1 = (r + 64) * ROWF + ch * 4;

    int nb = tid & 127;
    int kqb = tid >> 7;
    const float* pB = w2 + (size_t)e * H_DIM * C_DIM + n0 + nb;          // + k*C_DIM
    int sb0 = nb * ROWF + kqb * 4;
    int sb1 = nb * ROWF + (kqb + 2) * 4;

    float acc[4][4][4];
#pragma unroll
    for (int i = 0; i < 4; i++)
#pragma unroll
        for (int j = 0; j < 4; j++)
#pragma unroll
            for (int k = 0; k < 4; k++) acc[i][j][k] = 0.0f;

    const int NCHUNK = H_DIM / BK;   // 256

    {
        float4 va0 = *(const float4*)pA0;
        float4 va1 = *(const float4*)pA1;
        *(float4*)&sA[0][sa0] = va0;
        *(float4*)&sA[0][sa1] = va1;
        float4 vb0, vb1;
        vb0.x = rna_tf32(pB[(size_t)(kqb * 4 + 0) * C_DIM]);
        vb0.y = rna_tf32(pB[(size_t)(kqb * 4 + 1) * C_DIM]);
        vb0.z = rna_tf32(pB[(size_t)(kqb * 4 + 2) * C_DIM]);
        vb0.w = rna_tf32(pB[(size_t)(kqb * 4 + 3) * C_DIM]);
        vb1.x = rna_tf32(pB[(size_t)((kqb + 2) * 4 + 0) * C_DIM]);
        vb1.y = rna_tf32(pB[(size_t)((kqb + 2) * 4 + 1) * C_DIM]);
        vb1.z = rna_tf32(pB[(size_t)((kqb + 2) * 4 + 2) * C_DIM]);
        vb1.w = rna_tf32(pB[(size_t)((kqb + 2) * 4 + 3) * C_DIM]);
        *(float4*)&sB[0][sb0] = vb0;
        *(float4*)&sB[0][sb1] = vb1;
    }
    __syncthreads();

    for (int c = 0; c < NCHUNK; c++) {
        int buf = c & 1;
        float4 va0, va1, vb0, vb1;
        if (c + 1 < NCHUNK) {
            int k0 = (c + 1) * BK;
            va0 = *(const float4*)(pA0 + k0);
            va1 = *(const float4*)(pA1 + k0);
            vb0.x = rna_tf32(pB[(size_t)(k0 + kqb * 4 + 0) * C_DIM]);
            vb0.y = rna_tf32(pB[(size_t)(k0 + kqb * 4 + 1) * C_DIM]);
            vb0.z = rna_tf32(pB[(size_t)(k0 + kqb * 4 + 2) * C_DIM]);
            vb0.w = rna_tf32(pB[(size_t)(k0 + kqb * 4 + 3) * C_DIM]);
            vb1.x = rna_tf32(pB[(size_t)(k0 + (kqb + 2) * 4 + 0) * C_DIM]);
            vb1.y = rna_tf32(pB[(size_t)(k0 + (kqb + 2) * 4 + 1) * C_DIM]);
            vb1.z = rna_tf32(pB[(size_t)(k0 + (kqb + 2) * 4 + 2) * C_DIM]);
            vb1.w = rna_tf32(pB[(size_t)(k0 + (kqb + 2) * 4 + 3) * C_DIM]);
        }

        uint32_t bA = buf ? baseA1 : baseA0;
        uint32_t bB = buf ? baseB1 : baseB0;
#pragma unroll
        for (int ks = 0; ks < 2; ks++) {
            uint32_t a[4][4], b[2][4];
#pragma unroll
            for (int tm = 0; tm < 4; tm++) LDSM4(a[tm], bA + aoff[tm] + ks * 32);
#pragma unroll
            for (int tp = 0; tp < 2; tp++) LDSM4(b[tp], bB + boff[tp] + ks * 32);
#pragma unroll
            for (int tm = 0; tm < 4; tm++)
#pragma unroll
                for (int tn = 0; tn < 4; tn++)
                    MMA_TF32(acc[tm][tn], a[tm], b[tn >> 1][(tn & 1) * 2], b[tn >> 1][(tn & 1) * 2 + 1]);
        }

        if (c + 1 < NCHUNK) {
            int nbuf = buf ^ 1;
            *(float4*)&sA[nbuf][sa0] = va0;
            *(float4*)&sA[nbuf][sa1] = va1;
            *(float4*)&sB[nbuf][sb0] = vb0;
            *(float4*)&sB[nbuf][sb1] = vb1;
        }
        __syncthreads();
    }

    // Epilogue: bias, gate, atomic scatter into y
    const float* b2e = b2 + (size_t)e * C_DIM;
    int r0 = lane >> 2, cb = (lane & 3) * 2;
#pragma unroll
    for (int tm = 0; tm < 4; tm++) {
#pragma unroll
        for (int half = 0; half < 2; half++) {
            int rr = wm + tm * 16 + r0 + half * 8;
            int m = m0 + rr;
            if (m >= kept) continue;
            int   tok  = s_tok[rr];
            float gate = s_gate[rr];
            float* yrow = y + (size_t)tok * C_DIM;
#pragma unroll
            for (int tn = 0; tn < 4; tn++) {
                int col = n0 + wn + tn * 8 + cb;
                float v0 = (acc[tm][tn][half * 2]     + b2e[col])     * gate;
                float v1 = (acc[tm][tn][half * 2 + 1] + b2e[col + 1]) * gate;
                atomicAdd(&yrow[col],     v0);
                atomicAdd(&yrow[col + 1], v1);
            }
        }
    }
}

// ---------------------------------------------------------------------------
// 5) Aux loss
// ---------------------------------------------------------------------------
__global__ void aux_kernel(float* __restrict__ out, int aux_idx) {
    if (threadIdx.x == 0 && blockIdx.x == 0) {
        float tot = 0.0f;
        for (int e = 0; e < E_NUM; e++) tot += (float)g_kept[e];
        float aux = 0.0f;
        for (int e = 0; e < E_NUM; e++) {
            float mean_p = g_probsum[e] / (float)S_TOT;
            float frac   = (float)g_kept[e] / (tot + 1e-9f);
            aux += mean_p * frac;
        }
        out[aux_idx] = aux * (float)E_NUM;
    }
}

// ---------------------------------------------------------------------------
// Launch
// ---------------------------------------------------------------------------
extern "C" void kernel_launch(void* const* d_in, const int* in_sizes, int n_in,
                              void* d_out, int out_size) {
    const float* x   = (const float*)d_in[0];
    const float* rw  = (const float*)d_in[1];
    const float* rb  = (const float*)d_in[2];
    const float* w1  = (const float*)d_in[3];
    const float* b1  = (const float*)d_in[4];
    const float* w2  = (const float*)d_in[5];
    const float* b2  = (const float*)d_in[6];
    float* out = (float*)d_out;

    int ny = out_size - 1;   // y elements; last element = aux loss

    zero_kernel<<<1024, 256>>>(out, ny);
    router_kernel<<<S_TOT / 8, 256>>>(x, rw, rb);
    capacity_kernel<<<E_NUM, 256>>>();
    {
        dim3 grid(H_DIM / BN, CAPACITY / BM, E_NUM);   // 32 x 20 x 8
        gemm1_mma<<<grid, 256>>>(x, w1, b1);
    }
    {
        dim3 grid(C_DIM / BN, CAPACITY / BM, E_NUM);   // 8 x 20 x 8
        gemm2_mma<<<grid, 256>>>(w2, b2, out);
    }
    aux_kernel<<<1, 32>>>(out, ny);
}